// round 3
// baseline (speedup 1.0000x reference)
#include <cuda_runtime.h>
#include <math.h>

// Problem shape (fixed by the reference)
#define BB 64
#define SS 4096
#define DD 1024
#define SPLIT 16
#define CHUNK (SS / SPLIT)      // 256 rows per CTA
#define THREADS 256             // 256 threads * float4 = 1024 floats = one row
#define RG 4                    // rows per group (batched reduction)

// Split-K scratch (allocation-free rule: __device__ globals)
__device__ float g_part_m[BB * SPLIT];
__device__ float g_part_l[BB * SPLIT];
__device__ float4 g_part_acc[BB * SPLIT * (DD / 4)];

__global__ __launch_bounds__(THREADS)
void pool_partial_kernel(const float* __restrict__ x,
                         const int* __restrict__ mask,
                         const float* __restrict__ w)
{
    const int b     = blockIdx.x;
    const int chunk = blockIdx.y;
    const int s0    = chunk * CHUNK;
    const int tid   = threadIdx.x;
    const int lane  = tid & 31;
    const int warp  = tid >> 5;

    __shared__ unsigned short sh_valid[CHUNK];
    __shared__ int sh_nvalid;
    __shared__ float sh_red[2][RG][8];   // [phase][row-in-group][warp]

    // --- Deterministic mask compaction (warp 0 only) ---
    if (warp == 0) {
        int base = 0;
        const int* mrow = mask + (size_t)b * SS + s0;
        #pragma unroll 4
        for (int j = 0; j < CHUNK; j += 32) {
            int mv = mrow[j + lane];
            unsigned bal = __ballot_sync(0xffffffffu, mv != 0);
            if (mv != 0) {
                int pos = base + __popc(bal & ((1u << lane) - 1u));
                sh_valid[pos] = (unsigned short)(j + lane);
            }
            base += __popc(bal);
        }
        if (lane == 0) sh_nvalid = base;
    }
    __syncthreads();
    const int nv = sh_nvalid;

    // w slice for this thread's 4 dims
    const float4 wv = reinterpret_cast<const float4*>(w)[tid];

    const float4* __restrict__ xb =
        reinterpret_cast<const float4*>(x) + (size_t)b * SS * (DD / 4);

    float  m   = -INFINITY;
    float  l   = 0.0f;
    float4 acc = make_float4(0.f, 0.f, 0.f, 0.f);

    if (nv > 0) {
        // index of group-slot i, clamped to last valid row (padded slots
        // load a real row but contribute score = -inf -> pc = 0)
        const int last = nv - 1;
        const int nvg  = (nv + RG - 1) & ~(RG - 1);

        float4 nxt[RG];
        #pragma unroll
        for (int r = 0; r < RG; r++) {
            int i = r > last ? last : r;
            nxt[r] = xb[(size_t)(s0 + sh_valid[i]) * (DD / 4) + tid];
        }

        for (int g = 0; g < nvg; g += RG) {
            float4 cur[RG];
            #pragma unroll
            for (int r = 0; r < RG; r++) cur[r] = nxt[r];

            // prefetch next group (MLP = 4)
            if (g + RG < nvg) {
                #pragma unroll
                for (int r = 0; r < RG; r++) {
                    int i = g + RG + r; if (i > last) i = last;
                    nxt[r] = xb[(size_t)(s0 + sh_valid[i]) * (DD / 4) + tid];
                }
            }

            // 4 partial dots, warp-reduced (independent shuffle chains)
            float pd[RG];
            #pragma unroll
            for (int r = 0; r < RG; r++)
                pd[r] = cur[r].x * wv.x + cur[r].y * wv.y
                      + cur[r].z * wv.z + cur[r].w * wv.w;
            #pragma unroll
            for (int o = 16; o > 0; o >>= 1) {
                #pragma unroll
                for (int r = 0; r < RG; r++)
                    pd[r] += __shfl_xor_sync(0xffffffffu, pd[r], o);
            }

            const int p = (g >> 2) & 1;  // double-buffered slots -> 1 barrier/group
            if (lane == 0) {
                #pragma unroll
                for (int r = 0; r < RG; r++) sh_red[p][r][warp] = pd[r];
            }
            __syncthreads();

            float score[RG];
            #pragma unroll
            for (int r = 0; r < RG; r++) {
                float s = sh_red[p][r][0] + sh_red[p][r][1]
                        + sh_red[p][r][2] + sh_red[p][r][3]
                        + sh_red[p][r][4] + sh_red[p][r][5]
                        + sh_red[p][r][6] + sh_red[p][r][7];
                score[r] = (g + r < nv) ? s : -INFINITY;
            }

            // batched online-softmax update
            float gm = fmaxf(fmaxf(score[0], score[1]),
                             fmaxf(score[2], score[3]));
            float mn    = fmaxf(m, gm);
            float scale = __expf(m - mn);    // first group: exp(-inf)=0
            float eg    = __expf(gm - mn);
            float pc[RG], psum = 0.f;
            #pragma unroll
            for (int r = 0; r < RG; r++) {
                pc[r] = __expf(score[r] - gm) * eg;
                psum += pc[r];
            }
            l = l * scale + psum;
            acc.x = acc.x * scale + pc[0]*cur[0].x + pc[1]*cur[1].x
                                  + pc[2]*cur[2].x + pc[3]*cur[3].x;
            acc.y = acc.y * scale + pc[0]*cur[0].y + pc[1]*cur[1].y
                                  + pc[2]*cur[2].y + pc[3]*cur[3].y;
            acc.z = acc.z * scale + pc[0]*cur[0].z + pc[1]*cur[1].z
                                  + pc[2]*cur[2].z + pc[3]*cur[3].z;
            acc.w = acc.w * scale + pc[0]*cur[0].w + pc[1]*cur[1].w
                                  + pc[2]*cur[2].w + pc[3]*cur[3].w;
            m = mn;
        }
    }

    // write split-K partial
    const int pidx = b * SPLIT + chunk;
    if (tid == 0) { g_part_m[pidx] = m; g_part_l[pidx] = l; }
    g_part_acc[(size_t)pidx * (DD / 4) + tid] = acc;
}

__global__ __launch_bounds__(THREADS)
void pool_combine_kernel(float* __restrict__ out)
{
    const int b   = blockIdx.x;
    const int tid = threadIdx.x;

    float M = -INFINITY;
    #pragma unroll
    for (int j = 0; j < SPLIT; j++)
        M = fmaxf(M, g_part_m[b * SPLIT + j]);

    float  L = 0.0f;
    float4 o = make_float4(0.f, 0.f, 0.f, 0.f);
    #pragma unroll
    for (int j = 0; j < SPLIT; j++) {
        const int pidx = b * SPLIT + j;
        float e = __expf(g_part_m[pidx] - M);   // empty chunk: exp(-inf)=0
        L += e * g_part_l[pidx];
        float4 a = g_part_acc[(size_t)pidx * (DD / 4) + tid];
        o.x += e * a.x; o.y += e * a.y; o.z += e * a.z; o.w += e * a.w;
    }
    float inv = 1.0f / L;
    o.x *= inv; o.y *= inv; o.z *= inv; o.w *= inv;
    reinterpret_cast<float4*>(out)[(size_t)b * (DD / 4) + tid] = o;
}

extern "C" void kernel_launch(void* const* d_in, const int* in_sizes, int n_in,
                              void* d_out, int out_size)
{
    const float* x    = (const float*)d_in[0];
    const int*   mask = (const int*)d_in[1];
    const float* w    = (const float*)d_in[2];
    float*       out  = (float*)d_out;

    dim3 grid(BB, SPLIT);
    pool_partial_kernel<<<grid, THREADS>>>(x, mask, w);
    pool_combine_kernel<<<BB, THREADS>>>(out);
}